// round 3
// baseline (speedup 1.0000x reference)
#include <cuda_runtime.h>

// HardLinearAttention — algebraic collapse of P@Z@M@Z^T@Q@Z.
// d=1024, n=8192, Z is (2d+1, n+1) = (2049, 8193) float32.
//
//   v[j]  = sum_{k<8192} Z[j,k] * Z[2048,k]          (j < 1024)
//   r[k]  = sum_{j<1024} v[j] * (Z[1024+j,k] - Z[j,k])
//   out   = Z;  out[2048,k] += (alpha/8192) * r[k]

#define D       1024
#define NCOLS   8192
#define S       8193          // n+1 (row stride) — odd, so rows are 4B-aligned only
#define JCHUNKS 16
#define JPER    (D / JCHUNKS) // 64

__device__ float g_v[D];
__device__ float g_part[JCHUNKS * S];

// ---------------- kernel 1: v[j] = dot(Z[j, 0:8192], Z[2048, 0:8192]) ----
// Row stream vectorized (LDG.128) with per-row alignment phase; u row is
// L2-resident (re-read by all 1024 blocks) so scalar loads are fine.
__global__ void __launch_bounds__(256) k_compute_v(const float* __restrict__ Z) {
    const int j = blockIdx.x;                       // 0..1023
    const float* __restrict__ row = Z + (size_t)j * S;
    const float* __restrict__ u   = Z + (size_t)2048 * S;

    const int p  = (4 - (j & 3)) & 3;               // first 16B-aligned index
    const int nv = (NCOLS - p) >> 2;                // # of float4 in the row
    const int tail0 = p + 4 * nv;                   // first tail index

    float a0 = 0.f, a1 = 0.f, a2 = 0.f, a3 = 0.f;

    // head (< p elems) and tail (< 4 elems), handled by a few threads
    if (threadIdx.x < p)
        a0 += row[threadIdx.x] * u[threadIdx.x];
    if (threadIdx.x >= 4 && threadIdx.x < 4 + (NCOLS - tail0)) {
        const int k = tail0 + (threadIdx.x - 4);
        a1 += row[k] * u[k];
    }

    const float4* __restrict__ rv = (const float4*)(row + p);
    #pragma unroll 4
    for (int i = threadIdx.x; i < nv; i += 256) {
        const float4 r4 = rv[i];
        const int k = p + 4 * i;
        a0 += r4.x * u[k];
        a1 += r4.y * u[k + 1];
        a2 += r4.z * u[k + 2];
        a3 += r4.w * u[k + 3];
    }
    float acc = (a0 + a2) + (a1 + a3);

    // warp reduce
    #pragma unroll
    for (int o = 16; o > 0; o >>= 1)
        acc += __shfl_down_sync(0xffffffffu, acc, o);

    __shared__ float s[8];
    const int lane = threadIdx.x & 31;
    const int w    = threadIdx.x >> 5;
    if (lane == 0) s[w] = acc;
    __syncthreads();
    if (w == 0) {
        acc = (lane < 8) ? s[lane] : 0.f;
        #pragma unroll
        for (int o = 4; o > 0; o >>= 1)
            acc += __shfl_down_sync(0xffffffffu, acc, o);
        if (lane == 0) g_v[j] = acc;
    }
}

// ---------------- kernel 2: copy rows 0..2047 + partial r accumulation ---
// grid = (ceil(S/256), JCHUNKS); each thread owns one column k.
// Streaming hints: out is write-once (evict-first), Z rows are read-once here.
__global__ void __launch_bounds__(256) k_copy_acc(const float* __restrict__ Z,
                                                  float* __restrict__ out) {
    const int jc = blockIdx.y;
    const int k  = blockIdx.x * 256 + threadIdx.x;

    __shared__ float vs[JPER];
    if (threadIdx.x < JPER) vs[threadIdx.x] = g_v[jc * JPER + threadIdx.x];
    __syncthreads();

    if (k >= S) return;

    const int j0 = jc * JPER;
    float acc = 0.f;
    #pragma unroll 8
    for (int jj = 0; jj < JPER; jj++) {
        const size_t ia = (size_t)(j0 + jj) * S + k;
        const size_t ib = (size_t)(j0 + jj + D) * S + k;
        const float a = __ldcs(Z + ia);
        const float b = __ldcs(Z + ib);
        __stcs(out + ia, a);
        __stcs(out + ib, b);
        acc += vs[jj] * (b - a);
    }
    g_part[(size_t)jc * S + k] = acc;
}

// ---------------- kernel 3: reduce partials, write final row 2048 --------
__global__ void __launch_bounds__(256) k_final(const float* __restrict__ Z,
                                               const float* __restrict__ alpha,
                                               float* __restrict__ out) {
    const int k = blockIdx.x * 256 + threadIdx.x;
    if (k >= S) return;
    float sum = 0.f;
    #pragma unroll
    for (int jc = 0; jc < JCHUNKS; jc++)
        sum += __ldcs(g_part + (size_t)jc * S + k);
    const float scale = alpha[0] / (float)NCOLS;
    out[(size_t)2048 * S + k] = Z[(size_t)2048 * S + k] + scale * sum;
}

extern "C" void kernel_launch(void* const* d_in, const int* in_sizes, int n_in,
                              void* d_out, int out_size) {
    const float* Z     = (const float*)d_in[0];
    const float* alpha = (const float*)d_in[1];
    float* out         = (float*)d_out;

    k_compute_v<<<D, 256>>>(Z);

    dim3 g2((S + 255) / 256, JCHUNKS);
    k_copy_acc<<<g2, 256>>>(Z, out);

    k_final<<<(S + 255) / 256, 256>>>(Z, alpha, out);
}

// round 5
// speedup vs baseline: 1.0876x; 1.0876x over previous
#include <cuda_runtime.h>

// HardLinearAttention — algebraic collapse of P@Z@M@Z^T@Q@Z.
// d=1024, n=8192, Z is (2d+1, n+1) = (2049, 8193) float32.
//
//   v[j]  = sum_{k<8192} Z[j,k] * Z[2048,k]          (j < 1024)
//   r[k]  = sum_{j<1024} v[j] * (Z[1024+j,k] - Z[j,k])   (k <= 8192)
//   out   = Z;  out[2048,k] += (alpha/8192) * r[k]

#define D       1024
#define NCOLS   8192
#define S       8193           // row stride (odd -> rows only 4B aligned)
#define JCHUNKS 64
#define JPER    16             // rows-pairs per chunk
#define BW      8208           // padded width for overflow partials

__device__ float g_v[D];
__device__ float g_A[JCHUNKS][NCOLS];   // partial r, columns 0..8191 (exact slots)
__device__ float g_B[JCHUNKS][BW];      // partial r, overflow slots (cols>=4, col%4!=3, incl 8192)

// ---------------- kernel 1: v[j] = dot(Z[j,0:8192], Z[2048,0:8192]) ------
// Block b handles rows {b, b+512} (equal phase). u is staged into smem
// PRE-SHIFTED by the phase so both row loads and the u load are 16B aligned.
__global__ void __launch_bounds__(256) k_compute_v(const float* __restrict__ Z) {
    __shared__ __align__(16) float su[NCOLS];
    __shared__ float r0s[8], r1s[8];

    const int b   = blockIdx.x;               // 0..511
    const int tid = threadIdx.x;
    const int p   = (4 - (b & 3)) & 3;        // first 16B-aligned col in row b
    const float* __restrict__ u = Z + (size_t)2048 * S;

    // su[t] = u[t+p], zero beyond col 8191 (M zeroes col n; also guards OOB)
    for (int t = tid; t < NCOLS; t += 256) {
        const int idx = t + p;
        su[t] = (idx < NCOLS) ? u[idx] : 0.f;
    }
    __syncthreads();

    const float* __restrict__ ra = Z + (size_t)b * S + p;          // 16B aligned
    const float* __restrict__ rb = Z + (size_t)(b + 512) * S + p;  // 16B aligned

    float acc0 = 0.f, acc1 = 0.f;
    if (tid < p) {   // head cols 0..p-1
        acc0 += Z[(size_t)b * S + tid] * u[tid];
        acc1 += Z[(size_t)(b + 512) * S + tid] * u[tid];
    }

    #pragma unroll 2
    for (int i = tid; i < 2048; i += 256) {
        const float4 s4 = *(const float4*)(su + 4 * i);
        const float4 a4 = *(const float4*)(ra + 4 * i);  // may read past col 8191; su=0 masks it
        const float4 b4 = *(const float4*)(rb + 4 * i);
        acc0 += a4.x * s4.x + a4.y * s4.y + a4.z * s4.z + a4.w * s4.w;
        acc1 += b4.x * s4.x + b4.y * s4.y + b4.z * s4.z + b4.w * s4.w;
    }

    // block reduce (two values)
    #pragma unroll
    for (int o = 16; o > 0; o >>= 1) {
        acc0 += __shfl_down_sync(0xffffffffu, acc0, o);
        acc1 += __shfl_down_sync(0xffffffffu, acc1, o);
    }
    const int lane = tid & 31, w = tid >> 5;
    if (lane == 0) { r0s[w] = acc0; r1s[w] = acc1; }
    __syncthreads();
    if (w == 0) {
        acc0 = (lane < 8) ? r0s[lane] : 0.f;
        acc1 = (lane < 8) ? r1s[lane] : 0.f;
        #pragma unroll
        for (int o = 4; o > 0; o >>= 1) {
            acc0 += __shfl_down_sync(0xffffffffu, acc0, o);
            acc1 += __shfl_down_sync(0xffffffffu, acc1, o);
        }
        if (lane == 0) { g_v[b] = acc0; g_v[b + 512] = acc1; }
    }
}

// ---------------- kernel 2: fused copy (rows 0..2047) + partial r --------
// Thread gt owns float4 column slot [4*gt+P, 4*gt+P+4) per row, phase P is
// compile-time per sub-iteration (P cycles 0,3,2,1 with jj&3 -> static acc
// indices, no spills). acc[o] accumulates column 4*gt+o (o=0..6).
// gt==2047 runs scalar with bounds checks (covers col 8192).
// gt==0 additionally covers head cols 0..P-1.
template <int P>
__device__ __forceinline__ void proc_row(const float* __restrict__ Z,
                                         float* __restrict__ out,
                                         int j, float vj, int gt,
                                         float (&acc)[7]) {
    const size_t ba = (size_t)j * S;
    const size_t bb = ba + (size_t)D * S;

    if (gt < 2047) {
        const int c0 = 4 * gt + P;
        const float4 a4 = *(const float4*)(Z + ba + c0);
        const float4 b4 = *(const float4*)(Z + bb + c0);
        *(float4*)(out + ba + c0) = a4;
        *(float4*)(out + bb + c0) = b4;
        acc[P + 0] += vj * (b4.x - a4.x);
        acc[P + 1] += vj * (b4.y - a4.y);
        acc[P + 2] += vj * (b4.z - a4.z);
        acc[P + 3] += vj * (b4.w - a4.w);
    } else {
        #pragma unroll
        for (int s = 0; s <= 4; s++) {           // s=4 catches col 8192 when P==0
            const int col = 8188 + P + s;
            if (col <= 8192) {
                const float a = Z[ba + col];
                const float b = Z[bb + col];
                out[ba + col] = a;
                out[bb + col] = b;
                acc[col - 8188] += vj * (b - a);
            }
        }
    }
    if (P > 0 && gt == 0) {                      // head cols 0..P-1
        #pragma unroll
        for (int c = 0; c < P; c++) {
            const float a = Z[ba + c];
            const float b = Z[bb + c];
            out[ba + c] = a;
            out[bb + c] = b;
            acc[c] += vj * (b - a);
        }
    }
}

__global__ void __launch_bounds__(256) k_copy_acc(const float* __restrict__ Z,
                                                  float* __restrict__ out) {
    __shared__ float vs[JPER];
    const int jc = blockIdx.y;
    const int gt = blockIdx.x * 256 + threadIdx.x;   // 0..2047
    if (threadIdx.x < JPER) vs[threadIdx.x] = g_v[jc * JPER + threadIdx.x];
    __syncthreads();

    const int j0 = jc * JPER;   // multiple of 16 -> phase depends on jj&3 only
    float acc[7] = {0.f, 0.f, 0.f, 0.f, 0.f, 0.f, 0.f};

    #pragma unroll 1
    for (int jj = 0; jj < JPER; jj += 4) {
        proc_row<0>(Z, out, j0 + jj + 0, vs[jj + 0], gt, acc);
        proc_row<3>(Z, out, j0 + jj + 1, vs[jj + 1], gt, acc);
        proc_row<2>(Z, out, j0 + jj + 2, vs[jj + 2], gt, acc);
        proc_row<1>(Z, out, j0 + jj + 3, vs[jj + 3], gt, acc);
    }

    #pragma unroll
    for (int s = 0; s < 4; s++) g_A[jc][4 * gt + s] = acc[s];       // cols 0..8191
    #pragma unroll
    for (int o = 4; o < 7; o++) g_B[jc][4 * gt + o] = acc[o];       // cols 4..8194 (padded)
}

// ---------------- kernel 3: reduce partials, write row 2048 --------------
__global__ void __launch_bounds__(256) k_final(const float* __restrict__ Z,
                                               const float* __restrict__ alpha,
                                               float* __restrict__ out) {
    const int k = blockIdx.x * 256 + threadIdx.x;
    if (k > NCOLS) return;
    const bool useA = (k < NCOLS);
    const bool useB = (k >= 4) && ((k & 3) != 3);
    float sum = 0.f;
    #pragma unroll 8
    for (int jc = 0; jc < JCHUNKS; jc++) {
        if (useA) sum += g_A[jc][k];
        if (useB) sum += g_B[jc][k];
    }
    const float scale = alpha[0] / (float)NCOLS;
    out[(size_t)2048 * S + k] = Z[(size_t)2048 * S + k] + scale * sum;
}

extern "C" void kernel_launch(void* const* d_in, const int* in_sizes, int n_in,
                              void* d_out, int out_size) {
    const float* Z     = (const float*)d_in[0];
    const float* alpha = (const float*)d_in[1];
    float* out         = (float*)d_out;

    k_compute_v<<<512, 256>>>(Z);

    dim3 g2(8, JCHUNKS);                 // 8 * 256 threads = 2048 col slots
    k_copy_acc<<<g2, 256>>>(Z, out);

    k_final<<<(S + 255) / 256, 256>>>(Z, alpha, out);
}

// round 7
// speedup vs baseline: 1.5276x; 1.4045x over previous
#include <cuda_runtime.h>

// HardLinearAttention — algebraic collapse of P@Z@M@Z^T@Q@Z.
// d=1024, n=8192, Z is (2d+1, n+1) = (2049, 8193) float32.
//
//   v[j]  = sum_{k<8192} Z[j,k] * Z[2048,k]          (j < 1024)
//   r[k]  = sum_{j<1024} v[j] * (Z[1024+j,k] - Z[j,k])
//   out   = Z;  out[2048,k] += (alpha/8192) * r[k]

#define D       1024
#define NCOLS   8192
#define S       8193          // n+1 (row stride)
#define JCHUNKS 16
#define JPER    (D / JCHUNKS) // 64

__device__ float g_v[D];
__device__ float g_part[JCHUNKS * S];

// ---------------- kernel 1: v[j] = dot(Z[j, 0:8192], Z[2048, 0:8192]) ----
// Block b handles rows {b, b+512}: u[k] loaded once, reused for both rows.
// All loads scalar + fully coalesced; unroll 8 => ~24 loads in flight/thread.
__global__ void __launch_bounds__(256) k_compute_v(const float* __restrict__ Z) {
    const int b = blockIdx.x;                       // 0..511
    const float* __restrict__ ra = Z + (size_t)b * S;
    const float* __restrict__ rb = Z + (size_t)(b + 512) * S;
    const float* __restrict__ u  = Z + (size_t)2048 * S;

    float acc0 = 0.f, acc1 = 0.f;
    #pragma unroll 8
    for (int k = threadIdx.x; k < NCOLS; k += 256) {
        const float uk = u[k];
        acc0 += ra[k] * uk;
        acc1 += rb[k] * uk;
    }

    // block reduce (two values)
    #pragma unroll
    for (int o = 16; o > 0; o >>= 1) {
        acc0 += __shfl_down_sync(0xffffffffu, acc0, o);
        acc1 += __shfl_down_sync(0xffffffffu, acc1, o);
    }
    __shared__ float s0[8], s1[8];
    const int lane = threadIdx.x & 31;
    const int w    = threadIdx.x >> 5;
    if (lane == 0) { s0[w] = acc0; s1[w] = acc1; }
    __syncthreads();
    if (w == 0) {
        acc0 = (lane < 8) ? s0[lane] : 0.f;
        acc1 = (lane < 8) ? s1[lane] : 0.f;
        #pragma unroll
        for (int o = 4; o > 0; o >>= 1) {
            acc0 += __shfl_down_sync(0xffffffffu, acc0, o);
            acc1 += __shfl_down_sync(0xffffffffu, acc1, o);
        }
        if (lane == 0) { g_v[b] = acc0; g_v[b + 512] = acc1; }
    }
}

// ---------------- kernel 2: copy rows 0..2047 + partial r accumulation ---
// grid = (ceil(S/256), JCHUNKS); each thread owns one column k.
// Identical to the 37.3us version except unroll 4 -> 8.
__global__ void __launch_bounds__(256) k_copy_acc(const float* __restrict__ Z,
                                                  float* __restrict__ out) {
    const int jc = blockIdx.y;
    const int k  = blockIdx.x * 256 + threadIdx.x;

    __shared__ float vs[JPER];
    if (threadIdx.x < JPER) vs[threadIdx.x] = g_v[jc * JPER + threadIdx.x];
    __syncthreads();

    if (k >= S) return;

    const int j0 = jc * JPER;
    float acc = 0.f;
    #pragma unroll 8
    for (int jj = 0; jj < JPER; jj++) {
        const size_t ia = (size_t)(j0 + jj) * S + k;
        const size_t ib = (size_t)(j0 + jj + D) * S + k;
        const float a = Z[ia];
        const float b = Z[ib];
        out[ia] = a;
        out[ib] = b;
        acc += vs[jj] * (b - a);
    }
    g_part[(size_t)jc * S + k] = acc;
}

// ---------------- kernel 3: reduce partials, write final row 2048 --------
__global__ void __launch_bounds__(256) k_final(const float* __restrict__ Z,
                                               const float* __restrict__ alpha,
                                               float* __restrict__ out) {
    const int k = blockIdx.x * 256 + threadIdx.x;
    if (k >= S) return;
    float sum = 0.f;
    #pragma unroll
    for (int jc = 0; jc < JCHUNKS; jc++)
        sum += g_part[(size_t)jc * S + k];
    const float scale = alpha[0] / (float)NCOLS;
    out[(size_t)2048 * S + k] = Z[(size_t)2048 * S + k] + scale * sum;
}

extern "C" void kernel_launch(void* const* d_in, const int* in_sizes, int n_in,
                              void* d_out, int out_size) {
    const float* Z     = (const float*)d_in[0];
    const float* alpha = (const float*)d_in[1];
    float* out         = (float*)d_out;

    k_compute_v<<<512, 256>>>(Z);

    dim3 g2((S + 255) / 256, JCHUNKS);
    k_copy_acc<<<g2, 256>>>(Z, out);

    k_final<<<(S + 255) / 256, 256>>>(Z, alpha, out);
}